// round 14
// baseline (speedup 1.0000x reference)
#include <cuda_runtime.h>

// FWHT (11 stages, N=2048) + sign flip on last quarter, batch 16384.
// kernel3 dataflow (2 warps/row, 32 fp32/thread, swap-shuffles, one smem
// half-exchange), made PERSISTENT (no wave-transition bubbles) with
// register-free L2 prefetch of the next row and streaming (evict-first)
// output stores so the input stays resident in L2 across graph replays.
//
// Bits: i0,i1=k0,k1 ; i2..i6=lane ; i7,i8,i9=k2,k3,k4 ; i10=warp half.
//   1) radix-4 on k0,k1            (register-local)
//   2) butterflies on k2,k3,k4     (register-local)
//   3) 5 swap-shuffle stages for lane bits (1 SHFL per register pair)
//   4) STS scrambled->linear (padded), named barrier (warp pair),
//      LDS both halves + bit-10 butterfly + sign/scale + STG.128 (.cs),
//      named barrier (smem reuse).

__global__ void __launch_bounds__(256, 4)
fwht_sign_kernel6(const float* __restrict__ in, float* __restrict__ out, int rows) {
    __shared__ float sbuf[8][1056];          // 4 pairs x 2 halves x (1024+32 pad)

    const int warp     = threadIdx.x >> 5;
    const int lane     = threadIdx.x & 31;
    const int pairLoc  = warp >> 1;          // 0..3
    const int half     = warp & 1;           // index bit 10
    const int pairGlb  = blockIdx.x * 4 + pairLoc;
    const int pairStr  = gridDim.x * 4;

    float* sbOwn = sbuf[pairLoc * 2 + half];
    const float* slo = sbuf[pairLoc * 2 + 0];
    const float* shi = sbuf[pairLoc * 2 + 1];
    const int scatBase = (lane & 3) + (lane >> 2) * 132;

    const float S = 0.022097086912079612f;   // (1/sqrt(2))^11

    for (int row = pairGlb; row < rows; row += pairStr) {
        const float4* __restrict__ src = reinterpret_cast<const float4*>(in)
                                       + (size_t)row * 512 + half * 256;

        // Register-free prefetch of NEXT row into L2 (warms ~4KB per warp).
        const int nrow = row + pairStr;
        if (nrow < rows) {
            const char* np = reinterpret_cast<const char*>(
                reinterpret_cast<const float4*>(in) + (size_t)nrow * 512 + half * 256);
            #pragma unroll
            for (int r = 0; r < 8; r++) {
                const char* p = np + r * 512 + (lane & 3) * 128;  // 4 lines per 512B
                asm volatile("prefetch.global.L2 [%0];" :: "l"(p));
            }
        }

        // Coalesced load of this row: 8 x LDG.128.
        float v[32];
        #pragma unroll
        for (int r = 0; r < 8; r++) {
            float4 f = src[r * 32 + lane];
            v[4*r+0] = f.x; v[4*r+1] = f.y; v[4*r+2] = f.z; v[4*r+3] = f.w;
        }

        // Bits 0,1: radix-4 inside each float4.
        #pragma unroll
        for (int q = 0; q < 32; q += 4) {
            float a0 = v[q+0], a1 = v[q+1], a2 = v[q+2], a3 = v[q+3];
            float b0 = a0 + a1, b1 = a0 - a1, b2 = a2 + a3, b3 = a2 - a3;
            v[q+0] = b0 + b2;
            v[q+1] = b1 + b3;
            v[q+2] = b0 - b2;
            v[q+3] = b1 - b3;
        }

        // Bits 7,8,9: register-local butterflies (bits k2,k3,k4).
        #pragma unroll
        for (int m = 4; m <= 16; m <<= 1) {
            #pragma unroll
            for (int k = 0; k < 32; k++) {
                if (k & m) continue;
                float a = v[k], b = v[k|m];
                v[k]   = a + b;
                v[k|m] = a - b;
            }
        }

        // Bits 2..6: swap-shuffle stages (1 SHFL per register pair).
        #pragma unroll
        for (int s = 0; s < 5; s++) {
            const int  h  = 1 << s;
            const bool up = (lane & h) != 0;
            #pragma unroll
            for (int k = 0; k < 32; k++) {
                if (k & h) continue;
                const int ko = k | h;
                float send = up ? v[k] : v[ko];
                float t = __shfl_xor_sync(0xffffffffu, send, h);
                float a = up ? t     : v[k];
                float b = up ? v[ko] : t;
                v[k]  = a + b;
                v[ko] = a - b;
            }
        }

        // Publish own half to smem, undoing the scramble (padded, conflict-free).
        // idx = (lane&3) | (k<<2) | ((lane>>2)<<7); addr = idx + 4*(idx>>7).
        #pragma unroll
        for (int k = 0; k < 32; k++)
            sbOwn[scatBase + 4 * k] = v[k];

        asm volatile("bar.sync %0, 64;" :: "r"(pairLoc + 1) : "memory");

        // Bit-10 butterfly + sign + scale + streaming coalesced store.
        {
            float4* dst = reinterpret_cast<float4*>(out)
                        + (size_t)row * 512 + half * 256;
            #pragma unroll
            for (int g = 0; g < 8; g++) {
                const int a = g * 132 + lane * 4;      // conflict-free LDS.128
                float4 lo = *reinterpret_cast<const float4*>(slo + a);
                float4 hi = *reinterpret_cast<const float4*>(shi + a);
                const float s = (half == 1 && g >= 4) ? -S : S;
                float4 o;
                if (half == 0) {
                    o.x = (lo.x + hi.x) * s; o.y = (lo.y + hi.y) * s;
                    o.z = (lo.z + hi.z) * s; o.w = (lo.w + hi.w) * s;
                } else {
                    o.x = (lo.x - hi.x) * s; o.y = (lo.y - hi.y) * s;
                    o.z = (lo.z - hi.z) * s; o.w = (lo.w - hi.w) * s;
                }
                __stcs(&dst[g * 32 + lane], o);        // evict-first: keep input in L2
            }
        }

        // Protect smem buffer before next iteration's scatter.
        asm volatile("bar.sync %0, 64;" :: "r"(pairLoc + 1) : "memory");
    }
}

extern "C" void kernel_launch(void* const* d_in, const int* in_sizes, int n_in,
                              void* d_out, int out_size) {
    const float* x = (const float*)d_in[0];
    float* out = (float*)d_out;
    const int rows = in_sizes[0] / 2048;     // 16384
    // Persistent grid: 148 SMs x 4 blocks resident (launch_bounds 256,4).
    const int blocks = 148 * 4;
    fwht_sign_kernel6<<<blocks, 256>>>(x, out, rows);
}

// round 15
// speedup vs baseline: 1.1772x; 1.1772x over previous
#include <cuda_runtime.h>

// FWHT (11 stages, N=2048) + sign flip on last quarter, batch 16384.
// ONE ROW PER 64-THREAD BLOCK (one warp pair). 32 fp32/thread.
// kernel3 dataflow: swap-shuffles for lane bits, one smem half-exchange for
// bit 10. Tiny blocks = fine-grained scheduling (up to 16 resident/SM),
// trivial 2-warp __syncthreads, no bounds checks. Streaming output stores
// (__stcs) keep the (L2-resident) input from being evicted by the output.
//
// Bits: i0,i1=k0,k1 ; i2..i6=lane ; i7,i8,i9=k2,k3,k4 ; i10=warp.
//   1) radix-4 on k0,k1            (register-local)
//   2) butterflies on k2,k3,k4     (register-local)
//   3) 5 swap-shuffle stages for lane bits (1 SHFL per register pair)
//   4) STS scrambled->linear (padded), __syncthreads,
//      LDS both halves + bit-10 butterfly + sign/scale + STG.128 (.cs).

__global__ void __launch_bounds__(64, 16)
fwht_sign_kernel7(const float* __restrict__ in, float* __restrict__ out) {
    __shared__ float sbuf[2][1056];          // 2 halves x (1024 + 32 pad)

    const int half = threadIdx.x >> 5;       // index bit 10
    const int lane = threadIdx.x & 31;
    const int row  = blockIdx.x;

    const float4* __restrict__ src =
        reinterpret_cast<const float4*>(in) + (size_t)row * 512 + half * 256;

    // Coalesced load: 8 x LDG.128 (512B contiguous per warp instr).
    float v[32];
    #pragma unroll
    for (int r = 0; r < 8; r++) {
        float4 f = src[r * 32 + lane];
        v[4*r+0] = f.x; v[4*r+1] = f.y; v[4*r+2] = f.z; v[4*r+3] = f.w;
    }

    // Bits 0,1: radix-4 inside each float4.
    #pragma unroll
    for (int q = 0; q < 32; q += 4) {
        float a0 = v[q+0], a1 = v[q+1], a2 = v[q+2], a3 = v[q+3];
        float b0 = a0 + a1, b1 = a0 - a1, b2 = a2 + a3, b3 = a2 - a3;
        v[q+0] = b0 + b2;
        v[q+1] = b1 + b3;
        v[q+2] = b0 - b2;
        v[q+3] = b1 - b3;
    }

    // Bits 7,8,9: register-local butterflies (register bits k2,k3,k4).
    #pragma unroll
    for (int m = 4; m <= 16; m <<= 1) {
        #pragma unroll
        for (int k = 0; k < 32; k++) {
            if (k & m) continue;
            float a = v[k], b = v[k|m];
            v[k]   = a + b;
            v[k|m] = a - b;
        }
    }

    // Bits 2..6: swap-shuffle stages (1 SHFL per register pair).
    #pragma unroll
    for (int s = 0; s < 5; s++) {
        const int  h  = 1 << s;
        const bool up = (lane & h) != 0;
        #pragma unroll
        for (int k = 0; k < 32; k++) {
            if (k & h) continue;
            const int ko = k | h;
            float send = up ? v[k] : v[ko];
            float t = __shfl_xor_sync(0xffffffffu, send, h);
            float a = up ? t     : v[k];
            float b = up ? v[ko] : t;
            v[k]  = a + b;
            v[ko] = a - b;
        }
    }

    // Publish own half to smem, undoing the scramble (padded, conflict-free).
    // idx = (lane&3) | (k<<2) | ((lane>>2)<<7); addr = idx + 4*(idx>>7).
    {
        float* sb = sbuf[half];
        const int base = (lane & 3) + (lane >> 2) * 132;
        #pragma unroll
        for (int k = 0; k < 32; k++)
            sb[base + 4 * k] = v[k];
    }

    __syncthreads();   // 2 warps only

    // Bit-10 butterfly + sign + scale + streaming coalesced store.
    {
        const float* slo = sbuf[0];
        const float* shi = sbuf[1];
        float4* dst = reinterpret_cast<float4*>(out) + (size_t)row * 512 + half * 256;
        const float S = 0.022097086912079612f;   // (1/sqrt(2))^11

        #pragma unroll
        for (int g = 0; g < 8; g++) {
            const int a = g * 132 + lane * 4;    // conflict-free LDS.128
            float4 lo = *reinterpret_cast<const float4*>(slo + a);
            float4 hi = *reinterpret_cast<const float4*>(shi + a);
            const float s = (half == 1 && g >= 4) ? -S : S;
            float4 o;
            if (half == 0) {
                o.x = (lo.x + hi.x) * s; o.y = (lo.y + hi.y) * s;
                o.z = (lo.z + hi.z) * s; o.w = (lo.w + hi.w) * s;
            } else {
                o.x = (lo.x - hi.x) * s; o.y = (lo.y - hi.y) * s;
                o.z = (lo.z - hi.z) * s; o.w = (lo.w - hi.w) * s;
            }
            __stcs(&dst[g * 32 + lane], o);      // evict-first: protect L2-resident input
        }
    }
}

extern "C" void kernel_launch(void* const* d_in, const int* in_sizes, int n_in,
                              void* d_out, int out_size) {
    const float* x = (const float*)d_in[0];
    float* out = (float*)d_out;
    const int rows = in_sizes[0] / 2048;     // 16384
    fwht_sign_kernel7<<<rows, 64>>>(x, out);
}